// round 1
// baseline (speedup 1.0000x reference)
#include <cuda_runtime.h>
#include <cuda_fp16.h>
#include <cstdint>

// Problem constants
#define P_PIX 32768            // H*W = 128*256
#define MODEL_DIM 256

// ---------------- scratch (static device globals; no allocation) -------------
__device__ __half g_H [128u * 32768u];          //  8 MB  hidden of demand MLP
__device__ __half g_X [256u * 32768u];          // 16 MB  query_state (fp16)
__device__ __half g_Q [256u * 32768u];          // 16 MB  q
__device__ __half g_KV[4u * 512u * 32768u];     // 128 MB k (rows 0..255) | v (rows 256..511) per collaborator
__device__ __half g_A [256u * 32768u];          // 16 MB  attention output

// ---------------- PTX helpers ------------------------------------------------
__device__ __forceinline__ void ldmx4(uint32_t& r0, uint32_t& r1, uint32_t& r2, uint32_t& r3, uint32_t addr) {
    asm volatile("ldmatrix.sync.aligned.m8n8.x4.shared.b16 {%0,%1,%2,%3}, [%4];\n"
                 : "=r"(r0), "=r"(r1), "=r"(r2), "=r"(r3) : "r"(addr));
}
__device__ __forceinline__ void ldmx4t(uint32_t& r0, uint32_t& r1, uint32_t& r2, uint32_t& r3, uint32_t addr) {
    asm volatile("ldmatrix.sync.aligned.m8n8.x4.trans.shared.b16 {%0,%1,%2,%3}, [%4];\n"
                 : "=r"(r0), "=r"(r1), "=r"(r2), "=r"(r3) : "r"(addr));
}
__device__ __forceinline__ void mma16816(float* d, const uint32_t* a, uint32_t b0, uint32_t b1) {
    asm volatile("mma.sync.aligned.m16n8k16.row.col.f32.f16.f16.f32 "
                 "{%0,%1,%2,%3}, {%4,%5,%6,%7}, {%8,%9}, {%0,%1,%2,%3};\n"
                 : "+f"(d[0]), "+f"(d[1]), "+f"(d[2]), "+f"(d[3])
                 : "r"(a[0]), "r"(a[1]), "r"(a[2]), "r"(a[3]), "r"(b0), "r"(b1));
}

// ---------------- demand-encoder hidden layer: h = relu(W1 d + b1) -----------
__global__ __launch_bounds__(256)
void hid_kernel(const float* __restrict__ D, const float* __restrict__ w1,
                const float* __restrict__ b1, __half* __restrict__ Hout)
{
    int t = blockIdx.x * blockDim.x + threadIdx.x;   // 128 * P threads
    int p = t & (P_PIX - 1);
    int c = t >> 15;
    float h = b1[c]
            + w1[c * 3 + 0] * D[p]
            + w1[c * 3 + 1] * D[P_PIX + p]
            + w1[c * 3 + 2] * D[2 * P_PIX + p];
    Hout[(size_t)c * P_PIX + p] = __float2half_rn(fmaxf(h, 0.f));
}

// ---------------- generic tensor-core GEMM -----------------------------------
// C[M, Ntot] = Wfp32[M, K] * B[K, Ntot]  (+ bias[M]) (+ add1 + add2)  -> half/float
// A rows < Msplit come from A0/bias0, else A1/bias1 (stacked wk;wv).
// B/C support a batch dimension: n = g*batchN + p, address = base + g*batchStride + row*ld + p
constexpr int BM = 128, BN = 128, BK = 32;
constexpr int PADA = 8, PADB = 8;

template<bool B_HALF, bool ADD2, bool OUT_HALF>
__global__ __launch_bounds__(256)
void gemm_tc(const float* __restrict__ A0, const float* __restrict__ A1, int Msplit,
             const void* __restrict__ Bv,
             const float* __restrict__ bias0, const float* __restrict__ bias1,
             const float* __restrict__ add1, const float* __restrict__ add2,
             void* __restrict__ Cv,
             int M, int Ntot, int K, int ldb, size_t bBatch, int batchN,
             int ldc, size_t cBatch)
{
    __shared__ __half As[BM][BK + PADA];
    __shared__ __half Bs[BK][BN + PADB];

    const int tid  = threadIdx.x;
    const int lane = tid & 31;
    const int warp = tid >> 5;
    const int warp_row = (warp & 3) * 32;   // 4 warps along M
    const int warp_col = (warp >> 2) * 64;  // 2 warps along N

    const int mtile0 = blockIdx.x * BM;
    const int ntile0 = blockIdx.y * BN;
    const int g  = ntile0 / batchN;
    const int p0 = ntile0 - g * batchN;

    float acc[2][8][4];
    #pragma unroll
    for (int i = 0; i < 2; i++)
        #pragma unroll
        for (int j = 0; j < 8; j++)
            #pragma unroll
            for (int t = 0; t < 4; t++) acc[i][j][t] = 0.f;

    for (int k0 = 0; k0 < K; k0 += BK) {
        // --- load A tile (fp32 -> fp16): 128x32, 1024 float4 slots, 4/thread
        #pragma unroll
        for (int i = 0; i < 4; i++) {
            int s  = tid + i * 256;
            int r  = s >> 3;
            int c4 = (s & 7) << 2;
            int gr = mtile0 + r;
            const float* Ap = (gr < Msplit) ? (A0 + (size_t)gr * K)
                                            : (A1 + (size_t)(gr - Msplit) * K);
            float4 f = *reinterpret_cast<const float4*>(Ap + k0 + c4);
            As[r][c4 + 0] = __float2half_rn(f.x);
            As[r][c4 + 1] = __float2half_rn(f.y);
            As[r][c4 + 2] = __float2half_rn(f.z);
            As[r][c4 + 3] = __float2half_rn(f.w);
        }
        // --- load B tile: 32x128
        if (B_HALF) {
            const __half* B = (const __half*)Bv + (size_t)g * bBatch;
            #pragma unroll
            for (int i = 0; i < 2; i++) {
                int s  = tid + i * 256;        // 512 uint4 slots
                int r  = s >> 4;
                int c8 = (s & 15) << 3;
                uint4 u = *reinterpret_cast<const uint4*>(B + (size_t)(k0 + r) * ldb + p0 + c8);
                *reinterpret_cast<uint4*>(&Bs[r][c8]) = u;
            }
        } else {
            const float* B = (const float*)Bv + (size_t)g * bBatch;
            #pragma unroll
            for (int i = 0; i < 4; i++) {
                int s  = tid + i * 256;        // 1024 float4 slots
                int r  = s >> 5;
                int c4 = (s & 31) << 2;
                float4 f = *reinterpret_cast<const float4*>(B + (size_t)(k0 + r) * ldb + p0 + c4);
                Bs[r][c4 + 0] = __float2half_rn(f.x);
                Bs[r][c4 + 1] = __float2half_rn(f.y);
                Bs[r][c4 + 2] = __float2half_rn(f.z);
                Bs[r][c4 + 3] = __float2half_rn(f.w);
            }
        }
        __syncthreads();

        #pragma unroll
        for (int kk = 0; kk < BK; kk += 16) {
            uint32_t a[2][4];
            #pragma unroll
            for (int mt = 0; mt < 2; mt++) {
                uint32_t addr = (uint32_t)__cvta_generic_to_shared(
                    &As[warp_row + mt * 16 + (lane & 15)][kk + ((lane >> 4) << 3)]);
                ldmx4(a[mt][0], a[mt][1], a[mt][2], a[mt][3], addr);
            }
            #pragma unroll
            for (int j = 0; j < 4; j++) {      // each covers two n8 tiles
                uint32_t b0, b1, b2, b3;
                uint32_t addr = (uint32_t)__cvta_generic_to_shared(
                    &Bs[kk + (lane & 15)][warp_col + j * 16 + ((lane >> 4) << 3)]);
                ldmx4t(b0, b1, b2, b3, addr);
                #pragma unroll
                for (int mt = 0; mt < 2; mt++) {
                    mma16816(acc[mt][2 * j],     a[mt], b0, b1);
                    mma16816(acc[mt][2 * j + 1], a[mt], b2, b3);
                }
            }
        }
        __syncthreads();
    }

    // --- epilogue
    __half* Ch = (__half*)Cv + (size_t)g * cBatch;
    float*  Cf = (float*)Cv  + (size_t)g * cBatch;
    #pragma unroll
    for (int mt = 0; mt < 2; mt++) {
        int r = warp_row + mt * 16 + (lane >> 2);
        #pragma unroll
        for (int rr = 0; rr < 2; rr++) {
            int gr = mtile0 + r + rr * 8;
            float bsv = (gr < Msplit) ? bias0[gr] : bias1[gr - Msplit];
            #pragma unroll
            for (int j = 0; j < 8; j++) {
                int c  = warp_col + j * 8 + ((lane & 3) << 1);
                int px = p0 + c;
                float v0 = acc[mt][j][rr * 2 + 0] + bsv;
                float v1 = acc[mt][j][rr * 2 + 1] + bsv;
                if (ADD2) {
                    size_t off = (size_t)gr * ldc + px;
                    v0 += add1[off]     + add2[off];
                    v1 += add1[off + 1] + add2[off + 1];
                }
                if (OUT_HALF) {
                    *reinterpret_cast<__half2*>(Ch + (size_t)gr * ldc + px) =
                        __floats2half2_rn(v0, v1);
                } else {
                    *reinterpret_cast<float2*>(Cf + (size_t)gr * ldc + px) =
                        make_float2(v0, v1);
                }
            }
        }
    }
}

// ---------------- per-pixel cross attention ----------------------------------
// scores[n] = (q . k_n) / sqrt(32); softmax over n (4); out = sum_n w_n v_n
__global__ __launch_bounds__(256)
void attn_kernel(const __half* __restrict__ Q, const __half* __restrict__ KV,
                 __half* __restrict__ A)
{
    int t = blockIdx.x * blockDim.x + threadIdx.x;  // 8 * P threads
    int p = t & (P_PIX - 1);
    int h = t >> 15;

    const __half* Qp = Q + (size_t)h * 32 * P_PIX + p;
    float q[32];
    #pragma unroll
    for (int d = 0; d < 32; d++) q[d] = __half2float(Qp[(size_t)d * P_PIX]);

    float s[4];
    #pragma unroll
    for (int n = 0; n < 4; n++) {
        const __half* Kp = KV + (size_t)n * 512 * P_PIX + (size_t)h * 32 * P_PIX + p;
        float a = 0.f;
        #pragma unroll
        for (int d = 0; d < 32; d++) a += q[d] * __half2float(Kp[(size_t)d * P_PIX]);
        s[n] = a * 0.17677669529663687f;   // 1/sqrt(32)
    }
    float mx = fmaxf(fmaxf(s[0], s[1]), fmaxf(s[2], s[3]));
    float w[4], sum = 0.f;
    #pragma unroll
    for (int n = 0; n < 4; n++) { w[n] = __expf(s[n] - mx); sum += w[n]; }
    float inv = 1.f / sum;
    #pragma unroll
    for (int n = 0; n < 4; n++) w[n] *= inv;

    __half* Ap = A + (size_t)h * 32 * P_PIX + p;
    #pragma unroll
    for (int d = 0; d < 32; d++) {
        float o = 0.f;
        #pragma unroll
        for (int n = 0; n < 4; n++)
            o += w[n] * __half2float(KV[(size_t)n * 512 * P_PIX
                                        + (size_t)(256 + h * 32 + d) * P_PIX + p]);
        Ap[(size_t)d * P_PIX] = __float2half_rn(o);
    }
}

// ---------------- launch -----------------------------------------------------
extern "C" void kernel_launch(void* const* d_in, const int* in_sizes, int n_in,
                              void* d_out, int out_size)
{
    const float* ego  = (const float*)d_in[0];
    const float* dem  = (const float*)d_in[1];
    const float* coll = (const float*)d_in[2];
    const float* w_d1 = (const float*)d_in[3];
    const float* b_d1 = (const float*)d_in[4];
    const float* w_d2 = (const float*)d_in[5];
    const float* b_d2 = (const float*)d_in[6];
    const float* wq   = (const float*)d_in[7];
    const float* bq   = (const float*)d_in[8];
    const float* wk   = (const float*)d_in[9];
    const float* bk   = (const float*)d_in[10];
    const float* wv   = (const float*)d_in[11];
    const float* bv   = (const float*)d_in[12];
    const float* wo   = (const float*)d_in[13];
    const float* bo   = (const float*)d_in[14];
    const float* pos  = (const float*)d_in[15];

    __half *H, *X, *Qb, *KV, *A;
    cudaGetSymbolAddress((void**)&H,  g_H);
    cudaGetSymbolAddress((void**)&X,  g_X);
    cudaGetSymbolAddress((void**)&Qb, g_Q);
    cudaGetSymbolAddress((void**)&KV, g_KV);
    cudaGetSymbolAddress((void**)&A,  g_A);

    const int P = P_PIX;

    // 1) demand hidden layer
    hid_kernel<<<(128 * P) / 256, 256>>>(dem, w_d1, b_d1, H);

    // 2) X = w_d2 @ H + b_d2 + ego + pos   (M=256, K=128) -> fp16
    gemm_tc<true, true, true><<<dim3(2, P / 128), 256>>>(
        w_d2, w_d2, 256, H, b_d2, b_d2, ego, pos,
        X, 256, P, 128, P, 0, P, P, 0);

    // 3) Q = wq @ X + bq                   (M=256, K=256) -> fp16
    gemm_tc<true, false, true><<<dim3(2, P / 128), 256>>>(
        wq, wq, 256, X, bq, bq, nullptr, nullptr,
        Qb, 256, P, 256, P, 0, P, P, 0);

    // 4) [K;V] = [wk;wv] @ collab + [bk;bv]  (M=512, N=4P, fp32 B) -> fp16
    gemm_tc<false, false, true><<<dim3(4, (4 * P) / 128), 256>>>(
        wk, wv, 256, coll, bk, bv, nullptr, nullptr,
        KV, 512, 4 * P, 256, P, (size_t)256 * P, P, P, (size_t)512 * P);

    // 5) attention over 4 collaborators per pixel/head
    attn_kernel<<<(8 * P) / 256, 256>>>(Qb, KV, A);

    // 6) out = wo @ A + bo -> fp32 d_out
    gemm_tc<true, false, false><<<dim3(2, P / 128), 256>>>(
        wo, wo, 256, A, bo, bo, nullptr, nullptr,
        d_out, 256, P, 256, P, 0, P, P, 0);
}